// round 13
// baseline (speedup 1.0000x reference)
#include <cuda_runtime.h>
#include <cstdint>

#define SEGSZ   1024         // floats per segment (8 float4 per lane)
#define MARGIN  256          // safety on predicted crossing (~3.4 sigma)
#define MAXSEG  32           // ceil(32000/1024)
#define NWARPS  4            // 128-thread CTAs

// ---- helpers -------------------------------------------------------------
__device__ __forceinline__ void seg_bounds(bool fwd, int s, int V, int& lo, int& hi) {
    if (fwd) { lo = s * SEGSZ; hi = min(V, lo + SEGSZ); }
    else     { hi = V - s * SEGSZ; lo = max(0, hi - SEGSZ); }
}

__device__ __forceinline__ void load_seg(float4 b[8], const float* __restrict__ prow,
                                         int lo, int hi, int lane) {
    if (hi - lo == SEGSZ) {
        // fast path: 8 back-to-back unguarded LDG.128
        const float* base = prow + lo + lane * 4;
        #pragma unroll
        for (int j = 0; j < 8; j++)
            b[j] = *reinterpret_cast<const float4*>(base + j * 128);
    } else {
        #pragma unroll
        for (int j = 0; j < 8; j++) {
            const int idx = lo + j * 128 + lane * 4;
            float4 a = make_float4(0.f, 0.f, 0.f, 0.f);
            if (idx + 4 <= hi) a = *reinterpret_cast<const float4*>(prow + idx);
            else {
                if (idx + 0 < hi) a.x = prow[idx + 0];
                if (idx + 1 < hi) a.y = prow[idx + 1];
                if (idx + 2 < hi) a.z = prow[idx + 2];
            }
            b[j] = a;
        }
    }
}

__device__ __forceinline__ float seg_sum(const float4 b[8]) {
    return (((b[0].x + b[0].y) + (b[0].z + b[0].w)) + ((b[1].x + b[1].y) + (b[1].z + b[1].w)))
         + (((b[2].x + b[2].y) + (b[2].z + b[2].w)) + ((b[3].x + b[3].y) + (b[3].z + b[3].w)))
         + (((b[4].x + b[4].y) + (b[4].z + b[4].w)) + ((b[5].x + b[5].y) + (b[5].z + b[5].w)))
         + (((b[6].x + b[6].y) + (b[6].z + b[6].w)) + ((b[7].x + b[7].y) + (b[7].z + b[7].w)));
}

// ---------------------------------------------------------------------------
// Predicted-span inverse-CDF sampler, double-buffered Phase 1.
// One CTA (128 thr / 4 warps) per row.
//   sample = #{v : r > csum[v]},  csum monotone (p >= 0), sum(p) ~= 1.
// r <= 0.5: forward;  r > 0.5: backward with q = 1-r (suffix formulation).
// Phase 1: each warp walks its segments with NEXT-segment loads issued
//          BEFORE the current reduce (non-speculative: whole span is needed),
//          keeping 8-16 LDG.128 in flight per warp continuously.
// Phase 2: warp 0 scans <=32 segment sums, ballot-finds the crossing.
// Phase 3: warp 0 recounts the crossing segment (just read => L2 hit).
// Span miss (rare, ~3e-4/row) retries with the full direction.
// Output dtype float32 (samples <= 32000 exact in fp32).
// ---------------------------------------------------------------------------
__global__ void __launch_bounds__(128) sampler_kernel(
    const float* __restrict__ p, const float* __restrict__ rng,
    float* __restrict__ out, int V)
{
    const int row  = blockIdx.x;
    const int t    = threadIdx.x;
    const int lane = t & 31;
    const int warp = t >> 5;

    __shared__ float s_seg[MAXSEG];
    __shared__ int   s_cross;
    __shared__ float s_pexcl;

    const float r = __ldg(&rng[row]);
    const float* __restrict__ prow = p + (size_t)row * V;
    const bool  fwd = (r <= 0.5f);
    const float thr = fwd ? r : (1.0f - r);

    const int nseg_total = (V + SEGSZ - 1) / SEGSZ;
    int nseg = (int)((thr * (float)V + (float)MARGIN) * (1.0f / SEGSZ)) + 1;
    if (nseg > nseg_total) nseg = nseg_total;

    for (;;) {
        // ---- Phase 1: double-buffered segment sums over the span ----
        {
            int s = warp;
            if (s < nseg) {
                int lo, hi;
                seg_bounds(fwd, s, V, lo, hi);
                float4 cur[8];
                load_seg(cur, prow, lo, hi, lane);
                for (;;) {
                    const int sn = s + NWARPS;
                    const bool have_next = (sn < nseg);
                    float4 nxt[8];
                    if (have_next) {
                        seg_bounds(fwd, sn, V, lo, hi);
                        load_seg(nxt, prow, lo, hi, lane);   // in flight during reduce
                    }
                    float v = seg_sum(cur);
                    #pragma unroll
                    for (int d = 16; d > 0; d >>= 1)
                        v += __shfl_xor_sync(0xFFFFFFFFu, v, d);
                    if (lane == 0) s_seg[s] = v;
                    if (!have_next) break;
                    #pragma unroll
                    for (int j = 0; j < 8; j++) cur[j] = nxt[j];  // keeps nxt live
                    s = sn;
                }
            }
        }
        __syncthreads();

        // ---- Phase 2: warp 0 scans segment sums, finds crossing ----
        if (warp == 0) {
            float x = (lane < nseg) ? s_seg[lane] : 0.0f;
            float incl = x;
            #pragma unroll
            for (int d = 1; d < 32; d <<= 1) {
                float y = __shfl_up_sync(0xFFFFFFFFu, incl, d);
                if (lane >= d) incl += y;
            }
            const bool hit = (lane < nseg) &&
                             (fwd ? (incl >= thr) : (incl > thr));
            const unsigned m = __ballot_sync(0xFFFFFFFFu, hit);
            const int cross = m ? (__ffs(m) - 1) : -1;
            float pexcl = 0.0f;
            if (cross > 0) pexcl = __shfl_sync(0xFFFFFFFFu, incl, cross - 1);
            if (lane == 0) { s_cross = cross; s_pexcl = pexcl; }
        }
        __syncthreads();

        const int cross = s_cross;
        if (cross >= 0) break;
        if (nseg == nseg_total) {                  // whole direction below thr
            if (t == 0) out[row] = fwd ? (float)V : 0.0f;
            return;
        }
        nseg = nseg_total;                         // rare: prediction missed
        __syncthreads();
    }

    // ---- Phase 3: warp 0 recounts inside the crossing segment (L2 hit) ----
    if (warp != 0) return;
    const int cross = s_cross;
    float carry = s_pexcl;                         // fwd: prefix<lo; bwd: suffix>=hi
    int lo, hi;
    seg_bounds(fwd, cross, V, lo, hi);
    int cnt = 0;

    if (fwd) {
        #pragma unroll
        for (int j = 0; j < 8; j++) {
            const int idx = lo + j * 128 + lane * 4;
            float4 a = make_float4(0.f, 0.f, 0.f, 0.f);
            if (idx + 4 <= hi) a = *reinterpret_cast<const float4*>(prow + idx);
            else {
                if (idx + 0 < hi) a.x = prow[idx + 0];
                if (idx + 1 < hi) a.y = prow[idx + 1];
                if (idx + 2 < hi) a.z = prow[idx + 2];
            }
            const float s4 = (a.x + a.y) + (a.z + a.w);
            float scan = s4;
            #pragma unroll
            for (int d = 1; d < 32; d <<= 1) {
                float y = __shfl_up_sync(0xFFFFFFFFu, scan, d);
                if (lane >= d) scan += y;
            }
            const float c0 = carry + (scan - s4) + a.x;
            const float c1 = c0 + a.y;
            const float c2 = c1 + a.z;
            const float c3 = c2 + a.w;
            cnt += (idx + 0 < hi && c0 < thr);
            cnt += (idx + 1 < hi && c1 < thr);
            cnt += (idx + 2 < hi && c2 < thr);
            cnt += (idx + 3 < hi && c3 < thr);
            carry += __shfl_sync(0xFFFFFFFFu, scan, 31);
        }
        #pragma unroll
        for (int d = 16; d > 0; d >>= 1)
            cnt += __shfl_xor_sync(0xFFFFFFFFu, cnt, d);
        if (lane == 0) out[row] = (float)(lo + cnt);
    } else {
        #pragma unroll
        for (int j = 7; j >= 0; j--) {
            const int idx = lo + j * 128 + lane * 4;
            float4 a = make_float4(0.f, 0.f, 0.f, 0.f);
            if (idx + 4 <= hi) a = *reinterpret_cast<const float4*>(prow + idx);
            else {
                if (idx + 0 < hi) a.x = prow[idx + 0];
                if (idx + 1 < hi) a.y = prow[idx + 1];
                if (idx + 2 < hi) a.z = prow[idx + 2];
            }
            const float s4 = (a.x + a.y) + (a.z + a.w);
            float rs = s4;                         // reverse inclusive scan
            #pragma unroll
            for (int d = 1; d < 32; d <<= 1) {
                float y = __shfl_down_sync(0xFFFFFFFFu, rs, d);
                if (lane < 32 - d) rs += y;
            }
            const float rev_excl = rs - s4;
            const float sw = carry + rev_excl + a.w;   // suf[idx+3]
            const float sz = sw + a.z;                 // suf[idx+2]
            const float sy = sz + a.y;                 // suf[idx+1]
            const float sx = sy + a.x;                 // suf[idx]
            cnt += (idx + 3 < hi && sw > thr);
            cnt += (idx + 2 < hi && sz > thr);
            cnt += (idx + 1 < hi && sy > thr);
            cnt += (idx + 0 < hi && sx > thr);
            carry += __shfl_sync(0xFFFFFFFFu, rs, 0);
        }
        #pragma unroll
        for (int d = 16; d > 0; d >>= 1)
            cnt += __shfl_xor_sync(0xFFFFFFFFu, cnt, d);
        if (lane == 0) out[row] = (float)(lo + cnt - 1 + (carry > thr ? 1 : 0));
    }
}

extern "C" void kernel_launch(void* const* d_in, const int* in_sizes, int n_in,
                              void* d_out, int out_size) {
    // Resolve inputs by element count (p is the huge one, rng has `rows`).
    int ip = 0;
    for (int i = 1; i < n_in; i++)
        if (in_sizes[i] > in_sizes[ip]) ip = i;
    const float* p = (const float*)d_in[ip];

    const int rows = out_size;                       // B*T = 8192
    int ir = (ip == 0) ? 1 : 0;
    for (int i = 0; i < n_in; i++)
        if (i != ip && in_sizes[i] == rows) { ir = i; break; }
    const float* rng = (const float*)d_in[ir];

    float* out = (float*)d_out;                      // output dtype: float32

    const long long pelems = (long long)in_sizes[ip];
    const int V = (int)(pelems / rows);              // 32000

    sampler_kernel<<<rows, 128>>>(p, rng, out, V);
}

// round 14
// speedup vs baseline: 1.0346x; 1.0346x over previous
#include <cuda_runtime.h>
#include <cstdint>

#define SEGSZ   512          // floats per segment (4 float4 per lane)
#define MARGIN  384          // ~7.5 sigma of crossing-position estimator
#define NLANESEG 32          // segment sums live one-per-lane

__device__ int g_row_counter;
__global__ void reset_counter_kernel() { g_row_counter = 0; }

// ---------------------------------------------------------------------------
// Persistent warp-per-row bidirectional inverse-CDF sampler.
//   sample = #{v : r > csum[v]},  csum monotone (p >= 0), sum(p) ~= 1.
// fwd (r<=0.5): span = [0, nseg*512); bwd (r>0.5, q=1-r): span =
// [V-nseg*512, V) — both walked ASCENDING; all segments exactly full
// (V=32000 => bwd start is 128B-aligned), so the hot loop has zero guards.
// Phase 1: stream segments, 4 batched LDG.128/lane, xor-reduce, park the
//          segment sum in lane s's register (no smem, no syncs).
// Phase 2: in-warp scan (prefix fwd / suffix bwd) + ballot -> crossing seg.
// Phase 3: re-read crossing segment (L2 hit), ordered 512-elem count.
// Span miss (p ~ 1e-7/row): exact serial forward fallback.
// One warp per row via atomic work-stealing; no __syncthreads anywhere.
// Output dtype float32 (samples <= 32000 exact in fp32).
// ---------------------------------------------------------------------------
__global__ void __launch_bounds__(128) sampler_kernel(
    const float* __restrict__ p, const float* __restrict__ rng,
    float* __restrict__ out, int V, int rows)
{
    const int lane = threadIdx.x & 31;

    for (;;) {
        int row;
        if (lane == 0) row = atomicAdd(&g_row_counter, 1);
        row = __shfl_sync(0xFFFFFFFFu, row, 0);
        if (row >= rows) return;

        const float r = __ldg(&rng[row]);
        const float* __restrict__ prow = p + (size_t)row * V;
        const bool  fwd = (r <= 0.5f);
        const float thr = fwd ? r : (1.0f - r);

        int nseg = (int)((thr * (float)V + (float)MARGIN) * (1.0f / SEGSZ)) + 1;
        if (nseg > NLANESEG) nseg = NLANESEG;          // thr<=0.5 keeps margin >=384
        const int start = fwd ? 0 : (V - nseg * SEGSZ); // bwd: >0, 128B-aligned

        // ---- Phase 1: stream full segments; lane s holds segment s's sum ----
        float segsum = 0.0f;
        for (int s = 0; s < nseg; s++) {
            const float* base = prow + start + s * SEGSZ + lane * 4;
            float4 b0 = *reinterpret_cast<const float4*>(base + 0 * 128);
            float4 b1 = *reinterpret_cast<const float4*>(base + 1 * 128);
            float4 b2 = *reinterpret_cast<const float4*>(base + 2 * 128);
            float4 b3 = *reinterpret_cast<const float4*>(base + 3 * 128);
            float v = (((b0.x + b0.y) + (b0.z + b0.w)) + ((b1.x + b1.y) + (b1.z + b1.w)))
                    + (((b2.x + b2.y) + (b2.z + b2.w)) + ((b3.x + b3.y) + (b3.z + b3.w)));
            #pragma unroll
            for (int d = 16; d > 0; d >>= 1)
                v += __shfl_xor_sync(0xFFFFFFFFu, v, d);
            if (lane == s) segsum = v;
        }

        // ---- Phase 2: in-warp crossing search ----
        float x = (lane < nseg) ? segsum : 0.0f;
        int   sstar = -1;
        float carry = 0.0f;

        if (fwd) {
            float incl = x;
            #pragma unroll
            for (int d = 1; d < 32; d <<= 1) {
                float y = __shfl_up_sync(0xFFFFFFFFu, incl, d);
                if (lane >= d) incl += y;
            }
            const unsigned m = __ballot_sync(0xFFFFFFFFu, (lane < nseg) && (incl >= thr));
            if (m) {
                sstar = __ffs(m) - 1;
                carry = (sstar > 0) ? __shfl_sync(0xFFFFFFFFu, incl, sstar - 1) : 0.0f;
            }
        } else {
            float rs = x;                              // suffix (reverse) scan
            #pragma unroll
            for (int d = 1; d < 32; d <<= 1) {
                float y = __shfl_down_sync(0xFFFFFFFFu, rs, d);
                if (lane < 32 - d) rs += y;
            }
            const unsigned m = __ballot_sync(0xFFFFFFFFu, (lane < nseg) && (rs > thr));
            if (m) {
                sstar = 31 - __clz(m);                 // LAST segment with suffix > q
                const int cl = sstar + 1;
                carry = (cl < 32) ? __shfl_sync(0xFFFFFFFFu, rs, cl) : 0.0f;
            }
        }

        float res;
        if (sstar >= 0) {
            // ---- Phase 3: ordered count in the crossing segment (L2 hit) ----
            const int lo = start + sstar * SEGSZ;
            const float* base = prow + lo + lane * 4;
            int cnt = 0;
            if (fwd) {
                float c = carry;
                #pragma unroll
                for (int j = 0; j < 4; j++) {
                    float4 a = *reinterpret_cast<const float4*>(base + j * 128);
                    const float s4 = (a.x + a.y) + (a.z + a.w);
                    float scan = s4;
                    #pragma unroll
                    for (int d = 1; d < 32; d <<= 1) {
                        float y = __shfl_up_sync(0xFFFFFFFFu, scan, d);
                        if (lane >= d) scan += y;
                    }
                    const float c0 = c + (scan - s4) + a.x;
                    const float c1 = c0 + a.y;
                    const float c2 = c1 + a.z;
                    const float c3 = c2 + a.w;
                    cnt += (c0 < thr) + (c1 < thr) + (c2 < thr) + (c3 < thr);
                    c += __shfl_sync(0xFFFFFFFFu, scan, 31);
                }
                #pragma unroll
                for (int d = 16; d > 0; d >>= 1)
                    cnt += __shfl_xor_sync(0xFFFFFFFFu, cnt, d);
                res = (float)(lo + cnt);
            } else {
                float c = carry;                       // suffix beyond segment end
                #pragma unroll
                for (int j = 3; j >= 0; j--) {
                    float4 a = *reinterpret_cast<const float4*>(base + j * 128);
                    const float s4 = (a.x + a.y) + (a.z + a.w);
                    float rs2 = s4;                    // reverse inclusive scan
                    #pragma unroll
                    for (int d = 1; d < 32; d <<= 1) {
                        float y = __shfl_down_sync(0xFFFFFFFFu, rs2, d);
                        if (lane < 32 - d) rs2 += y;
                    }
                    const float rev_excl = rs2 - s4;
                    const float sw = c + rev_excl + a.w;   // suf[idx+3]
                    const float sz = sw + a.z;             // suf[idx+2]
                    const float sy = sz + a.y;             // suf[idx+1]
                    const float sx = sy + a.x;             // suf[idx]
                    cnt += (sw > thr) + (sz > thr) + (sy > thr) + (sx > thr);
                    c += __shfl_sync(0xFFFFFFFFu, rs2, 0);
                }
                #pragma unroll
                for (int d = 16; d > 0; d >>= 1)
                    cnt += __shfl_xor_sync(0xFFFFFFFFu, cnt, d);
                res = (float)(lo + cnt - 1);
            }
        } else {
            // ---- Fallback (astronomically rare): exact serial forward scan ----
            float acc = 0.0f;
            res = (float)V;
            for (int lo2 = 0; lo2 < V; lo2 += SEGSZ) {
                const int hi2 = min(V, lo2 + SEGSZ);
                float4 a[4];
                #pragma unroll
                for (int j = 0; j < 4; j++) {
                    const int idx = lo2 + j * 128 + lane * 4;
                    float4 t = make_float4(0.f, 0.f, 0.f, 0.f);
                    if (idx + 4 <= hi2) t = *reinterpret_cast<const float4*>(prow + idx);
                    else {
                        if (idx + 0 < hi2) t.x = prow[idx + 0];
                        if (idx + 1 < hi2) t.y = prow[idx + 1];
                        if (idx + 2 < hi2) t.z = prow[idx + 2];
                    }
                    a[j] = t;
                }
                float v = (((a[0].x + a[0].y) + (a[0].z + a[0].w))
                         + ((a[1].x + a[1].y) + (a[1].z + a[1].w)))
                        + (((a[2].x + a[2].y) + (a[2].z + a[2].w))
                         + ((a[3].x + a[3].y) + (a[3].z + a[3].w)));
                #pragma unroll
                for (int d = 16; d > 0; d >>= 1)
                    v += __shfl_xor_sync(0xFFFFFFFFu, v, d);
                if (acc + v >= r) {                    // crossing in this segment
                    float c = acc;
                    int cnt = 0;
                    #pragma unroll
                    for (int j = 0; j < 4; j++) {
                        const int idx = lo2 + j * 128 + lane * 4;
                        const float s4 = (a[j].x + a[j].y) + (a[j].z + a[j].w);
                        float scan = s4;
                        #pragma unroll
                        for (int d = 1; d < 32; d <<= 1) {
                            float y = __shfl_up_sync(0xFFFFFFFFu, scan, d);
                            if (lane >= d) scan += y;
                        }
                        const float c0 = c + (scan - s4) + a[j].x;
                        const float c1 = c0 + a[j].y;
                        const float c2 = c1 + a[j].z;
                        const float c3 = c2 + a[j].w;
                        cnt += (idx + 0 < hi2 && c0 < r);
                        cnt += (idx + 1 < hi2 && c1 < r);
                        cnt += (idx + 2 < hi2 && c2 < r);
                        cnt += (idx + 3 < hi2 && c3 < r);
                        c += __shfl_sync(0xFFFFFFFFu, scan, 31);
                    }
                    #pragma unroll
                    for (int d = 16; d > 0; d >>= 1)
                        cnt += __shfl_xor_sync(0xFFFFFFFFu, cnt, d);
                    res = (float)(lo2 + cnt);
                    break;
                }
                acc += v;
            }
        }

        if (lane == 0) out[row] = res;
    }
}

extern "C" void kernel_launch(void* const* d_in, const int* in_sizes, int n_in,
                              void* d_out, int out_size) {
    // Resolve inputs by element count (p is the huge one, rng has `rows`).
    int ip = 0;
    for (int i = 1; i < n_in; i++)
        if (in_sizes[i] > in_sizes[ip]) ip = i;
    const float* p = (const float*)d_in[ip];

    const int rows = out_size;                       // B*T = 8192
    int ir = (ip == 0) ? 1 : 0;
    for (int i = 0; i < n_in; i++)
        if (i != ip && in_sizes[i] == rows) { ir = i; break; }
    const float* rng = (const float*)d_in[ir];

    float* out = (float*)d_out;                      // output dtype: float32

    const long long pelems = (long long)in_sizes[ip];
    const int V = (int)(pelems / rows);              // 32000

    reset_counter_kernel<<<1, 1>>>();
    // persistent: ~12 CTAs/SM x 148 SMs; warps steal rows
    sampler_kernel<<<1776, 128>>>(p, rng, out, V, rows);
}